// round 4
// baseline (speedup 1.0000x reference)
#include <cuda_runtime.h>

// Problem constants
constexpr int B = 256;
constexpr int T = 2048;
constexpr int D = 64;     // input dim
constexpr int H = 25;     // LSTM units
constexpr int G = 100;    // 4 gates * H
constexpr long long ROWS = (long long)B * T;   // 524288

// Scratch for layer-1 input projections: [B*T][100] floats = ~210 MB
__device__ float g_xp[52428800];

// Packed fp32x2 FMA (Blackwell f32x2 pipe: 2 fp32 MACs per issue, full precision)
__device__ __forceinline__ float2 ffma2(float2 a, float2 b, float2 c) {
    float2 d;
    asm("fma.rn.f32x2 %0, %1, %2, %3;"
        : "=l"(reinterpret_cast<unsigned long long &>(d))
        : "l"(reinterpret_cast<unsigned long long &>(a)),
          "l"(reinterpret_cast<unsigned long long &>(b)),
          "l"(reinterpret_cast<unsigned long long &>(c)));
    return d;
}

__device__ __forceinline__ float sigm(float x) { return 1.0f / (1.0f + __expf(-x)); }

// ---------------------------------------------------------------------------
// Kernel 1: layer-1 input projections.
// xp[row][g*25+u] = sum_j x[row][j] * Wx_g[j][u] + b_g[u]
// Tile: 64 rows per block. x staged transposed in smem so consecutive rows are
// adjacent -> row-pair packed f32x2 accumulation (2 MACs / FMA instruction).
// ---------------------------------------------------------------------------
constexpr int XROWS = 64;

__global__ __launch_bounds__(256) void xproj_kernel(
    const float* __restrict__ x,
    const float* __restrict__ Wxi, const float* __restrict__ bi,
    const float* __restrict__ Wxf, const float* __restrict__ bf,
    const float* __restrict__ Wxc, const float* __restrict__ bc,
    const float* __restrict__ Wxo, const float* __restrict__ bo)
{
    __shared__ float Ws[D * G];     // combined weights, [j][c] layout
    __shared__ float xT[D][66];     // transposed x tile (stride 66: even + conflict pad)

    const int tid = threadIdx.x;
    const long long row0 = (long long)blockIdx.x * XROWS;

    // Stage combined gate weights [64][100]
    for (int idx = tid; idx < D * G; idx += 256) {
        int j = idx / G, c = idx % G;
        int g = c / H, u = c % H;
        const float* W = (g == 0) ? Wxi : (g == 1) ? Wxf : (g == 2) ? Wxc : Wxo;
        Ws[idx] = W[j * H + u];
    }
    // Stage x tile transposed (coalesced float4 loads)
    for (int idx = tid; idx < XROWS * 16; idx += 256) {
        int r = idx >> 4, jq = idx & 15;
        float4 v = *reinterpret_cast<const float4*>(&x[(row0 + r) * D + jq * 4]);
        xT[jq * 4 + 0][r] = v.x;
        xT[jq * 4 + 1][r] = v.y;
        xT[jq * 4 + 2][r] = v.z;
        xT[jq * 4 + 3][r] = v.w;
    }
    __syncthreads();

    if (tid < 200) {
        const int c  = tid % G;    // output column (gate*25+u)
        const int rg = tid / G;    // row-half: 32 rows each
        const int g = c / H, u = c % H;
        const float bias = ((g == 0) ? bi : (g == 1) ? bf : (g == 2) ? bc : bo)[u];

        float2 acc[16];
        #pragma unroll
        for (int k = 0; k < 16; k++) acc[k] = make_float2(0.f, 0.f);

        #pragma unroll 2
        for (int j = 0; j < D; j++) {
            float w = Ws[j * G + c];
            float2 wp = make_float2(w, w);
            const float2* xr = reinterpret_cast<const float2*>(&xT[j][rg * 32]);
            #pragma unroll
            for (int k = 0; k < 16; k++) acc[k] = ffma2(xr[k], wp, acc[k]);
        }

        float* outp = &g_xp[(row0 + rg * 32) * G + c];
        #pragma unroll
        for (int k = 0; k < 16; k++) {
            outp[(2 * k)     * G] = acc[k].x + bias;
            outp[(2 * k + 1) * G] = acc[k].y + bias;
        }
    }
}

// ---------------------------------------------------------------------------
// Kernel 2: fused 2-layer LSTM recurrence + output head.
// One block per batch element, 256 threads:
//   tid   0.. 99 : layer-1 gate (gate=tid/25, unit=tid%25), Wh column in regs
//   tid 128..227 : layer-2 gate for step t-1 (Wx2 + Wh2 columns in regs)
//   tid 228      : output head for step t-2
//   tid   0.. 24 : layer-1 cell combine (phase B), c1 in register
//   tid 128..152 : layer-2 cell combine (phase B), c2 in register
// h1/h2 double-buffered in smem; 2 barriers per step.
// ---------------------------------------------------------------------------
__global__ __launch_bounds__(256) void lstm_kernel(
    const float* __restrict__ Whi1, const float* __restrict__ Whf1,
    const float* __restrict__ Whc1, const float* __restrict__ Who1,
    const float* __restrict__ Wxi2, const float* __restrict__ Wxf2,
    const float* __restrict__ Wxc2, const float* __restrict__ Wxo2,
    const float* __restrict__ bi2,  const float* __restrict__ bf2,
    const float* __restrict__ bc2,  const float* __restrict__ bo2,
    const float* __restrict__ Whi2, const float* __restrict__ Whf2,
    const float* __restrict__ Whc2, const float* __restrict__ Who2,
    const float* __restrict__ Wout, const float* __restrict__ bout,
    float* __restrict__ out)
{
    __shared__ float h1s[2][32];   // double-buffered hidden, padded (idx 25..31 stay 0)
    __shared__ float h2s[2][32];
    __shared__ float g1s[128];     // layer-1 gate values [gate*25+u]
    __shared__ float g2s[128];     // layer-2 gate values

    const int tid = threadIdx.x;
    const int b   = blockIdx.x;

    // Zero hidden buffers (pad lanes included)
    for (int i = tid; i < 64; i += 256) {
        (&h1s[0][0])[i] = 0.f;
        (&h2s[0][0])[i] = 0.f;
    }

    // Role-dependent register weights (wA/wB shared across roles to cap regs)
    float2 wA[13], wB[13];
    float bias2 = 0.f, boV = 0.f;
    float c1 = 0.f, c2 = 0.f;
    int gate = 0;

    if (tid < 100) {
        gate = tid / 25;
        const int u = tid % 25;
        const float* W = (gate == 0) ? Whi1 : (gate == 1) ? Whf1 : (gate == 2) ? Whc1 : Who1;
        #pragma unroll
        for (int j = 0; j < 13; j++) {
            float lo = W[(2 * j) * 25 + u];
            float hi = (2 * j + 1 < 25) ? W[(2 * j + 1) * 25 + u] : 0.f;
            wA[j] = make_float2(lo, hi);
        }
    } else if (tid >= 128 && tid < 228) {
        const int l = tid - 128;
        gate = l / 25;
        const int u = l % 25;
        const float* WX = (gate == 0) ? Wxi2 : (gate == 1) ? Wxf2 : (gate == 2) ? Wxc2 : Wxo2;
        const float* WH = (gate == 0) ? Whi2 : (gate == 1) ? Whf2 : (gate == 2) ? Whc2 : Who2;
        bias2 = ((gate == 0) ? bi2 : (gate == 1) ? bf2 : (gate == 2) ? bc2 : bo2)[u];
        #pragma unroll
        for (int j = 0; j < 13; j++) {
            float xlo = WX[(2 * j) * 25 + u];
            float xhi = (2 * j + 1 < 25) ? WX[(2 * j + 1) * 25 + u] : 0.f;
            wA[j] = make_float2(xlo, xhi);
            float hlo = WH[(2 * j) * 25 + u];
            float hhi = (2 * j + 1 < 25) ? WH[(2 * j + 1) * 25 + u] : 0.f;
            wB[j] = make_float2(hlo, hhi);
        }
    } else if (tid == 228) {
        #pragma unroll
        for (int j = 0; j < 13; j++) {
            float lo = Wout[2 * j];
            float hi = (2 * j + 1 < 25) ? Wout[2 * j + 1] : 0.f;
            wA[j] = make_float2(lo, hi);
        }
        boV = bout[0];
    }
    __syncthreads();

    // Prefetch xp for step 0
    float xcur = 0.f;
    if (tid < 100) xcur = g_xp[((long long)b * T) * G + tid];

    for (int t = 0; t < T + 2; t++) {
        __syncthreads();   // prior phase-B hidden writes visible; gate arrays free

        // ---------------- Phase A: gate computations (pipelined layers) -----
        if (tid < 100) {
            float xv = xcur;
            if (t + 1 < T) xcur = g_xp[((long long)b * T + (t + 1)) * G + tid];
            if (t < T) {
                const float2* hp = reinterpret_cast<const float2*>(h1s[(t + 1) & 1]); // h1_{t-1}
                float2 acc = make_float2(xv, 0.f);
                #pragma unroll
                for (int j = 0; j < 13; j++) acc = ffma2(hp[j], wA[j], acc);
                float a = acc.x + acc.y;
                g1s[tid] = (gate == 2) ? tanhf(a) : sigm(a);
            }
        } else if (tid >= 128 && tid < 228) {
            if (t >= 1 && t <= T) {
                const int s = t - 1;
                const float2* xq = reinterpret_cast<const float2*>(h1s[s & 1]);        // h1_s
                const float2* hq = reinterpret_cast<const float2*>(h2s[(s + 1) & 1]);  // h2_{s-1}
                float2 acc = make_float2(bias2, 0.f);
                #pragma unroll
                for (int j = 0; j < 13; j++) acc = ffma2(xq[j], wA[j], acc);
                #pragma unroll
                for (int j = 0; j < 13; j++) acc = ffma2(hq[j], wB[j], acc);
                float a = acc.x + acc.y;
                g2s[tid - 128] = (gate == 2) ? tanhf(a) : sigm(a);
            }
        } else if (tid == 228) {
            if (t >= 2) {
                const int s = t - 2;
                const float2* hq = reinterpret_cast<const float2*>(h2s[s & 1]);        // h2_s
                float2 acc = make_float2(boV, 0.f);
                #pragma unroll
                for (int j = 0; j < 13; j++) acc = ffma2(hq[j], wA[j], acc);
                out[(long long)b * T + s] = sigm(acc.x + acc.y);
            }
        }

        __syncthreads();   // gates visible

        // ---------------- Phase B: cell-state combine ----------------------
        if (tid < 25) {
            if (t < T) {
                float gi = g1s[tid], gf = g1s[25 + tid], gg = g1s[50 + tid], go = g1s[75 + tid];
                c1 = gg * gi + gf * c1;
                h1s[t & 1][tid] = go * tanhf(c1);
            }
        } else if (tid >= 128 && tid < 153) {
            if (t >= 1 && t <= T) {
                const int u = tid - 128;
                float gi = g2s[u], gf = g2s[25 + u], gg = g2s[50 + u], go = g2s[75 + u];
                c2 = gg * gi + gf * c2;
                h2s[(t - 1) & 1][u] = go * tanhf(c2);
            }
        }
    }
}

// ---------------------------------------------------------------------------
// Host launcher. Input order is detected from in_sizes:
//   dict order      : x, Wout(25), bout(1), l1_*(12), l2_*(12)
//   signature order : x, l1_*(12), l2_*(12), Wout, bout
// Per-layer order: Wxi, bi, Whi, Wxf, bf, Whf, Wxc, bc, Whc, Wxo, bo, Who
// ---------------------------------------------------------------------------
extern "C" void kernel_launch(void* const* d_in, const int* in_sizes, int n_in,
                              void* d_out, int out_size) {
    const float* p[27];
    for (int i = 0; i < 27 && i < n_in; i++) p[i] = (const float*)d_in[i];
    const float* x = p[0];

    int l1, l2, iWout, ibout;
    if (n_in >= 3 && in_sizes[1] == H) {   // dict order (Wout right after x)
        iWout = 1; ibout = 2; l1 = 3; l2 = 15;
    } else {                                // reference-signature order
        l1 = 1; l2 = 13; iWout = 25; ibout = 26;
    }

    xproj_kernel<<<(int)(ROWS / XROWS), 256>>>(
        x,
        p[l1 + 0], p[l1 + 1],    // Wxi, bi
        p[l1 + 3], p[l1 + 4],    // Wxf, bf
        p[l1 + 6], p[l1 + 7],    // Wxc, bc
        p[l1 + 9], p[l1 + 10]);  // Wxo, bo

    lstm_kernel<<<B, 256>>>(
        p[l1 + 2], p[l1 + 5], p[l1 + 8], p[l1 + 11],     // l1 Whi, Whf, Whc, Who
        p[l2 + 0], p[l2 + 3], p[l2 + 6], p[l2 + 9],      // l2 Wxi, Wxf, Wxc, Wxo
        p[l2 + 1], p[l2 + 4], p[l2 + 7], p[l2 + 10],     // l2 bi, bf, bc, bo
        p[l2 + 2], p[l2 + 5], p[l2 + 8], p[l2 + 11],     // l2 Whi, Whf, Whc, Who
        p[iWout], p[ibout],
        (float*)d_out);
}